// round 2
// baseline (speedup 1.0000x reference)
#include <cuda_runtime.h>

typedef unsigned long long u64;
typedef unsigned int u32;

#define K_CODES 8192
#define EDIM 128
#define TM 128
#define TN 256
#define DK 16
#define SA 132            // As row stride (floats): [d][row], padded
#define SB 260            // Bs row stride (floats): [d][col], padded
#define SMEM_BYTES ((128*SA + 2*DK*SB) * 4 + TM * 8)

__device__ float  d_esq[K_CODES];
__device__ float  d_zsq[32768];
__device__ int    d_counts[K_CODES];
__device__ int    d_idx[32768];
__device__ double d_sumsq;

// ---------- helpers ----------
__device__ __forceinline__ u64 pack2(float lo, float hi) {
    u64 r; asm("mov.b64 %0, {%1, %2};" : "=l"(r) : "f"(lo), "f"(hi)); return r;
}
__device__ __forceinline__ u64 dup2(float v) {
    u64 r; asm("mov.b64 %0, {%1, %1};" : "=l"(r) : "f"(v)); return r;
}
__device__ __forceinline__ u64 ffma2(u64 a, u64 b, u64 c) {
    u64 d; asm("fma.rn.f32x2 %0, %1, %2, %3;" : "=l"(d) : "l"(a), "l"(b), "l"(c)); return d;
}
__device__ __forceinline__ void unpack2(u64 v, float& lo, float& hi) {
    asm("mov.b64 {%0, %1}, %2;" : "=f"(lo), "=f"(hi) : "l"(v));
}
// monotone float -> u32 key (ascending float order -> ascending uint order)
__device__ __forceinline__ u32 fkey(float s) {
    u32 b = __float_as_uint(s);
    return (b & 0x80000000u) ? ~b : (b | 0x80000000u);
}

// ---------- kernel 0a: |e_k|^2 + zero counts/sumsq ----------
__global__ void k_init(const float* __restrict__ emb) {
    int k = blockIdx.x * blockDim.x + threadIdx.x;
    if (k < K_CODES) {
        const float4* row = (const float4*)(emb + (size_t)k * EDIM);
        float s = 0.f;
#pragma unroll
        for (int i = 0; i < EDIM / 4; i++) {
            float4 v = row[i];
            s += v.x * v.x + v.y * v.y + v.z * v.z + v.w * v.w;
        }
        d_esq[k] = s;
        d_counts[k] = 0;
    }
    if (blockIdx.x == 0 && threadIdx.x == 0) d_sumsq = 0.0;
}

// ---------- kernel 0b: |z_n|^2 per row ----------
__global__ void k_zsq(const float* __restrict__ z) {
    int n = blockIdx.x * blockDim.x + threadIdx.x;
    const float4* row = (const float4*)(z + (size_t)n * EDIM);
    float s = 0.f;
#pragma unroll
    for (int i = 0; i < EDIM / 4; i++) {
        float4 v = row[i];
        s += v.x * v.x + v.y * v.y + v.z * v.z + v.w * v.w;
    }
    d_zsq[n] = s;
}

// ---------- kernel 1: fused GEMM + argmin (reference-exact quantization) ----------
extern "C" __global__ void __launch_bounds__(256, 1)
k_argmin(const float* __restrict__ z, const float* __restrict__ emb) {
    extern __shared__ float sm[];
    float* As = sm;                         // [128 d][SA] (row-indexed)
    float* Bs = sm + 128 * SA;              // [2][DK][SB] (col-indexed)
    u64* sbest = (u64*)(Bs + 2 * DK * SB);  // [TM]

    const int t  = threadIdx.x;
    const int tx = t & 15;                  // 0..15 -> col groups
    const int ty = t >> 4;                  // 0..15 -> row group of 8
    const int rowBase = blockIdx.x * TM;

    if (t < TM) sbest[t] = ~0ULL;

    // Load z tile [TM][128] -> As[d][row] (one-time transpose)
    {
        const float4* zg = (const float4*)(z + (size_t)rowBase * EDIM);
#pragma unroll
        for (int k = 0; k < 16; k++) {
            int pos = t + k * 256;          // 0..4095 float4 slots
            int row = pos >> 5;             // 32 float4 per row
            int d4  = pos & 31;
            float4 v = zg[(size_t)row * 32 + d4];
            As[(d4 * 4 + 0) * SA + row] = v.x;
            As[(d4 * 4 + 1) * SA + row] = v.y;
            As[(d4 * 4 + 2) * SA + row] = v.z;
            As[(d4 * 4 + 3) * SA + row] = v.w;
        }
    }
    __syncthreads();

    // per-thread row |z|^2 (rows ty*8 .. ty*8+7)
    float zs[8];
#pragma unroll
    for (int i = 0; i < 8; i++) zs[i] = d_zsq[rowBase + ty * 8 + i];

    u64 best[8];
#pragma unroll
    for (int i = 0; i < 8; i++) best[i] = ~0ULL;

    float4 breg[4];

    for (int tile = 0; tile < K_CODES / TN; tile++) {
        const int colBase = tile * TN;
        // prefetch chunk 0 of this tile's B (col = t, 16 d values)
        {
            const float4* eg = (const float4*)(emb + (size_t)(colBase + t) * EDIM);
#pragma unroll
            for (int q = 0; q < 4; q++) breg[q] = eg[q];
        }
        u64 acc[4][16];
#pragma unroll
        for (int p = 0; p < 4; p++)
#pragma unroll
            for (int j = 0; j < 16; j++) acc[p][j] = 0ULL;

#pragma unroll 1
        for (int c = 0; c < EDIM / DK; c++) {
            float* Bcur = Bs + (c & 1) * (DK * SB);
            __syncthreads();
            // store regs -> Bcur[d][col=t]  (conflict-free: consecutive cols)
#pragma unroll
            for (int q = 0; q < 4; q++) {
                Bcur[(q * 4 + 0) * SB + t] = breg[q].x;
                Bcur[(q * 4 + 1) * SB + t] = breg[q].y;
                Bcur[(q * 4 + 2) * SB + t] = breg[q].z;
                Bcur[(q * 4 + 3) * SB + t] = breg[q].w;
            }
            __syncthreads();
            if (c + 1 < EDIM / DK) {
                const float4* eg =
                    (const float4*)(emb + (size_t)(colBase + t) * EDIM + (c + 1) * DK);
#pragma unroll
                for (int q = 0; q < 4; q++) breg[q] = eg[q];
            }
            // compute 16 d-steps
#pragma unroll 4
            for (int dd = 0; dd < DK; dd++) {
                const float* ad = As + (c * DK + dd) * SA + ty * 8;
                float4 av0 = *(const float4*)(ad);
                float4 av1 = *(const float4*)(ad + 4);
                u64 a2[4];
                a2[0] = pack2(av0.x, av0.y);
                a2[1] = pack2(av0.z, av0.w);
                a2[2] = pack2(av1.x, av1.y);
                a2[3] = pack2(av1.z, av1.w);
                const float4* bd4 = (const float4*)(Bcur + dd * SB);
#pragma unroll
                for (int jb = 0; jb < 4; jb++) {
                    float4 bv = bd4[jb * 16 + tx];
                    float bvals[4] = {bv.x, bv.y, bv.z, bv.w};
#pragma unroll
                    for (int jq = 0; jq < 4; jq++) {
                        u64 bb = dup2(bvals[jq]);
#pragma unroll
                        for (int p = 0; p < 4; p++)
                            acc[p][jb * 4 + jq] = ffma2(a2[p], bb, acc[p][jb * 4 + jq]);
                    }
                }
            }
        }
        // epilogue: d = fl(fl(zsq + esq) - 2*dot)  -- matches reference rounding.
        // (2*dot is exact; FMA contraction of the subtract is bit-identical.)
#pragma unroll
        for (int jb = 0; jb < 4; jb++) {
#pragma unroll
            for (int jq = 0; jq < 4; jq++) {
                int colg = colBase + jb * 64 + tx * 4 + jq;
                float ev = d_esq[colg];
#pragma unroll
                for (int p = 0; p < 4; p++) {
                    float dlo, dhi;
                    unpack2(acc[p][jb * 4 + jq], dlo, dhi);
                    float tlo = zs[2 * p] + ev;        // fl(zsq + esq)
                    float thi = zs[2 * p + 1] + ev;
                    float slo = tlo - 2.f * dlo;       // fl(t - 2*dot)
                    float shi = thi - 2.f * dhi;
                    u64 plo = ((u64)fkey(slo) << 13) | (u32)colg;
                    u64 phi = ((u64)fkey(shi) << 13) | (u32)colg;
                    if (plo < best[2 * p])     best[2 * p]     = plo;
                    if (phi < best[2 * p + 1]) best[2 * p + 1] = phi;
                }
            }
        }
    }
    // reduce 16 threads/row via smem atomicMin
#pragma unroll
    for (int p = 0; p < 8; p++) atomicMin(&sbest[ty * 8 + p], best[p]);
    __syncthreads();
    if (t < TM) d_idx[rowBase + t] = (int)(sbest[t] & 0x1FFFULL);
}

// ---------- kernel 2: gather + straight-through out + sums + counts ----------
__global__ void k_gather(const float* __restrict__ z, const float* __restrict__ emb,
                         float* __restrict__ out) {
    __shared__ float red[8];
    int e4 = blockIdx.x * blockDim.x + threadIdx.x;  // float4 index
    int row = e4 >> 5;                                // 32 float4 per row
    int d4  = e4 & 31;
    int k = d_idx[row];
    float4 q  = ((const float4*)(emb + (size_t)k * EDIM))[d4];
    float4 zz = ((const float4*)z)[e4];
    float4 o;
    float s = 0.f, df;
    df = q.x - zz.x; o.x = zz.x + df; s += df * df;   // z + (z_q - z), fp-exact vs ref
    df = q.y - zz.y; o.y = zz.y + df; s += df * df;
    df = q.z - zz.z; o.z = zz.z + df; s += df * df;
    df = q.w - zz.w; o.w = zz.w + df; s += df * df;
    ((float4*)out)[e4] = o;
    if (d4 == 0) atomicAdd(&d_counts[k], 1);
#pragma unroll
    for (int off = 16; off; off >>= 1) s += __shfl_xor_sync(0xffffffffu, s, off);
    int lane = threadIdx.x & 31, w = threadIdx.x >> 5;
    if (lane == 0) red[w] = s;
    __syncthreads();
    if (threadIdx.x == 0) {
        float bs = 0.f;
#pragma unroll
        for (int i = 0; i < 8; i++) bs += red[i];
        atomicAdd(&d_sumsq, (double)bs);
    }
}

// ---------- kernel 3: perplexity + commit loss ----------
__global__ void k_final(float* __restrict__ out, int n_rows) {
    __shared__ float red[256];
    float acc = 0.f;
    float invN = 1.f / (float)n_rows;
    for (int k = threadIdx.x; k < K_CODES; k += 256) {
        float e = (float)d_counts[k] * invN;
        acc += e * logf(e + 1e-8f);
    }
    red[threadIdx.x] = acc;
    __syncthreads();
    for (int s = 128; s; s >>= 1) {
        if (threadIdx.x < s) red[threadIdx.x] += red[threadIdx.x + s];
        __syncthreads();
    }
    if (threadIdx.x == 0) {
        float m = (float)(d_sumsq / (double)((size_t)n_rows * EDIM));
        float commit = 0.25f * m + m;                 // BETA*mean + mean (same fwd value)
        float perp = expf(-red[0]);
        out[(size_t)n_rows * EDIM]     = commit;
        out[(size_t)n_rows * EDIM + 1] = perp;
    }
}

extern "C" void kernel_launch(void* const* d_in, const int* in_sizes, int n_in,
                              void* d_out, int out_size) {
    const float* z   = (const float*)d_in[0];
    const float* emb = (const float*)d_in[1];
    float* out = (float*)d_out;
    int n_rows = in_sizes[0] / EDIM;                  // 32768

    cudaFuncSetAttribute(k_argmin, cudaFuncAttributeMaxDynamicSharedMemorySize, SMEM_BYTES);

    k_init<<<K_CODES / 256, 256>>>(emb);
    k_zsq<<<n_rows / 256, 256>>>(z);
    k_argmin<<<n_rows / TM, 256, SMEM_BYTES>>>(z, emb);
    k_gather<<<(n_rows * (EDIM / 4)) / 256, 256>>>(z, emb, out);
    k_final<<<1, 256>>>(out, n_rows);
}

// round 4
// speedup vs baseline: 1.2398x; 1.2398x over previous
#include <cuda_runtime.h>

typedef unsigned long long u64;
typedef unsigned int u32;

#define K_CODES 8192
#define EDIM 128
#define TM 128
#define TN 128
#define N_TILES (K_CODES / TN)    // 64
#define SA 132                    // padded row stride (floats)
#define A_FLOATS (128 * SA)
#define STAGE_FLOATS (128 * SA)
#define SMEM_TOTAL ((A_FLOATS + 2 * STAGE_FLOATS + 128) * 4 + 128 * 8)

__device__ float  d_esq[K_CODES];
__device__ int    d_counts[K_CODES];
__device__ int    d_idx[32768];
__device__ double d_sumsq;

// ---------------- helpers ----------------
__device__ __forceinline__ u32 smem_u32(const void* p) {
    u32 a; asm("{ .reg .u64 t; cvta.to.shared.u64 t, %1; cvt.u32.u64 %0, t; }" : "=r"(a) : "l"(p));
    return a;
}
__device__ __forceinline__ u32 tf32b(float x) {
    u32 r; asm("cvt.rna.tf32.f32 %0, %1;" : "=r"(r) : "f"(x)); return r;
}
__device__ __forceinline__ u32 fkey(float s) {
    u32 b = __float_as_uint(s);
    return (b & 0x80000000u) ? ~b : (b | 0x80000000u);
}
__device__ __forceinline__ void cp16(u32 dst, const void* src) {
    asm volatile("cp.async.cg.shared.global [%0], [%1], 16;" :: "r"(dst), "l"(src) : "memory");
}
__device__ __forceinline__ void mma8(float* c, const u32* a, const u32* b) {
    asm volatile(
        "mma.sync.aligned.m16n8k8.row.col.f32.tf32.tf32.f32 "
        "{%0,%1,%2,%3}, {%4,%5,%6,%7}, {%8,%9}, {%0,%1,%2,%3};"
        : "+f"(c[0]), "+f"(c[1]), "+f"(c[2]), "+f"(c[3])
        : "r"(a[0]), "r"(a[1]), "r"(a[2]), "r"(a[3]), "r"(b[0]), "r"(b[1]));
}

// ---------- kernel 0: |e_k|^2 + zero counts/sumsq ----------
__global__ void k_init(const float* __restrict__ emb) {
    int k = blockIdx.x * blockDim.x + threadIdx.x;
    if (k < K_CODES) {
        const float4* row = (const float4*)(emb + (size_t)k * EDIM);
        float s = 0.f;
#pragma unroll
        for (int i = 0; i < EDIM / 4; i++) {
            float4 v = row[i];
            s += v.x * v.x + v.y * v.y + v.z * v.z + v.w * v.w;
        }
        d_esq[k] = s;
        d_counts[k] = 0;
    }
    if (blockIdx.x == 0 && threadIdx.x == 0) d_sumsq = 0.0;
}

// ---------- main: 3xTF32 mma.sync GEMM + grid-exact argmin ----------
extern "C" __global__ void __launch_bounds__(256, 1)
k_main(const float* __restrict__ z, const float* __restrict__ emb) {
    extern __shared__ float sm[];
    float* As    = sm;                              // [128][132] fp32 z-tile
    float* Bs    = sm + A_FLOATS;                   // 2 stages [128][132] fp32 emb tile
    float* zsmem = Bs + 2 * STAGE_FLOATS;           // [128] |z|^2
    u64*   sbest = (u64*)(zsmem + 128);             // [128]

    const int tid  = threadIdx.x;
    const int wid  = tid >> 5;
    const int lane = tid & 31;
    const int lr   = lane >> 2;                     // 0..7
    const int lc   = lane & 3;                      // 0..3
    const int wm   = (wid & 1) * 64;                // warp m offset
    const int wn   = (wid >> 1) * 32;               // warp n offset
    const int rowBase = blockIdx.x * TM;

    const u32 smb   = smem_u32(sm);
    const u32 bsOff = smb + A_FLOATS * 4;

    // ---- issue prefetch of tile 0 (async) ----
    {
        const float* src = emb;                     // tile 0 starts at colBase 0
#pragma unroll
        for (int i = 0; i < 16; i++) {
            int idx = tid + i * 256;                // 0..4095
            int r = idx >> 5, seg = idx & 31;
            cp16(bsOff + (u32)(r * (SA * 4) + seg * 16), src + r * EDIM + seg * 4);
        }
        asm volatile("cp.async.commit_group;" ::: "memory");
    }

    // ---- prologue: z rows -> As (fp32) + per-row |z|^2 (round-2-identical order) ----
    if (tid < 128) {
        const float4* zr = (const float4*)(z + (size_t)(rowBase + tid) * EDIM);
        float s = 0.f;
#pragma unroll
        for (int q = 0; q < 32; q++) {
            float4 v = zr[q];
            s += v.x * v.x + v.y * v.y + v.z * v.z + v.w * v.w;
            *(float4*)(As + tid * SA + q * 4) = v;
        }
        zsmem[tid] = s;
        sbest[tid] = ~0ULL;
    }
    __syncthreads();

    // per-thread row |z|^2 (8 rows owned by this thread)
    float zrow[4][2];
#pragma unroll
    for (int i = 0; i < 4; i++) {
        zrow[i][0] = zsmem[wm + i * 16 + lr];
        zrow[i][1] = zsmem[wm + i * 16 + lr + 8];
    }

    u64 best[4][2];
#pragma unroll
    for (int i = 0; i < 4; i++) { best[i][0] = ~0ULL; best[i][1] = ~0ULL; }

#pragma unroll 1
    for (int tile = 0; tile < N_TILES; tile++) {
        const int st = tile & 1;
        const int colBase = tile * TN;

        // prefetch esq for this thread's 8 columns (hidden behind mma)
        float eq[4][2];
#pragma unroll
        for (int j = 0; j < 4; j++) {
            int c0 = colBase + wn + j * 8 + 2 * lc;
            eq[j][0] = d_esq[c0];
            eq[j][1] = d_esq[c0 + 1];
        }

        // issue prefetch of next tile into other stage
        if (tile + 1 < N_TILES) {
            const float* src = emb + (size_t)(colBase + TN) * EDIM;
            u32 dstb = bsOff + (st ^ 1) * (STAGE_FLOATS * 4);
#pragma unroll
            for (int i = 0; i < 16; i++) {
                int idx = tid + i * 256;
                int r = idx >> 5, seg = idx & 31;
                cp16(dstb + (u32)(r * (SA * 4) + seg * 16), src + r * EDIM + seg * 4);
            }
            asm volatile("cp.async.commit_group;" ::: "memory");
            asm volatile("cp.async.wait_group 1;" ::: "memory");
        } else {
            asm volatile("cp.async.wait_group 0;" ::: "memory");
        }
        __syncthreads();

        const float* Bt = Bs + st * STAGE_FLOATS;

        float acc[4][4][4];
#pragma unroll
        for (int i = 0; i < 4; i++)
#pragma unroll
            for (int j = 0; j < 4; j++)
#pragma unroll
                for (int c = 0; c < 4; c++) acc[i][j][c] = 0.f;

#pragma unroll 1
        for (int kb = 0; kb < 16; kb++) {
            const int k0 = kb * 8;
            // A fragments (hi/lo tf32 derived on the fly)
            u32 ahi[4][4], alo[4][4];
#pragma unroll
            for (int i = 0; i < 4; i++) {
                const float* a0 = As + (wm + i * 16 + lr) * SA + k0;
                const float* a1 = a0 + 8 * SA;
                float x0 = a0[lc], x1 = a1[lc], x2 = a0[4 + lc], x3 = a1[4 + lc];
                ahi[i][0] = tf32b(x0); alo[i][0] = tf32b(x0 - __uint_as_float(ahi[i][0]));
                ahi[i][1] = tf32b(x1); alo[i][1] = tf32b(x1 - __uint_as_float(ahi[i][1]));
                ahi[i][2] = tf32b(x2); alo[i][2] = tf32b(x2 - __uint_as_float(ahi[i][2]));
                ahi[i][3] = tf32b(x3); alo[i][3] = tf32b(x3 - __uint_as_float(ahi[i][3]));
            }
            // B fragments
            u32 bhi[4][2], blo[4][2];
#pragma unroll
            for (int j = 0; j < 4; j++) {
                const float* bp = Bt + (wn + j * 8 + lr) * SA + k0;
                float y0 = bp[lc], y1 = bp[4 + lc];
                bhi[j][0] = tf32b(y0); blo[j][0] = tf32b(y0 - __uint_as_float(bhi[j][0]));
                bhi[j][1] = tf32b(y1); blo[j][1] = tf32b(y1 - __uint_as_float(bhi[j][1]));
            }
            // 3-term split MMAs
#pragma unroll
            for (int i = 0; i < 4; i++)
#pragma unroll
                for (int j = 0; j < 4; j++) mma8(acc[i][j], ahi[i], bhi[j]);
#pragma unroll
            for (int i = 0; i < 4; i++)
#pragma unroll
                for (int j = 0; j < 4; j++) mma8(acc[i][j], ahi[i], blo[j]);
#pragma unroll
            for (int i = 0; i < 4; i++)
#pragma unroll
                for (int j = 0; j < 4; j++) mma8(acc[i][j], alo[i], bhi[j]);
        }

        // epilogue: d = fl(fl(zsq+esq) - 2*dot), grid-exact vs reference
#pragma unroll
        for (int i = 0; i < 4; i++) {
#pragma unroll
            for (int j = 0; j < 4; j++) {
                int cg0 = colBase + wn + j * 8 + 2 * lc;
#pragma unroll
                for (int s = 0; s < 2; s++) {
                    float t0 = zrow[i][s] + eq[j][0];
                    float t1 = zrow[i][s] + eq[j][1];
                    float d0 = t0 - 2.f * acc[i][j][2 * s + 0];
                    float d1 = t1 - 2.f * acc[i][j][2 * s + 1];
                    u64 k0 = ((u64)fkey(d0) << 13) | (u32)cg0;
                    u64 k1 = ((u64)fkey(d1) << 13) | (u32)(cg0 + 1);
                    if (k0 < best[i][s]) best[i][s] = k0;
                    if (k1 < best[i][s]) best[i][s] = k1;
                }
            }
        }
        __syncthreads();
    }

    // reduce across threads sharing a row
#pragma unroll
    for (int i = 0; i < 4; i++) {
        atomicMin(&sbest[wm + i * 16 + lr],     best[i][0]);
        atomicMin(&sbest[wm + i * 16 + lr + 8], best[i][1]);
    }
    __syncthreads();
    if (tid < 128) d_idx[rowBase + tid] = (int)(sbest[tid] & 0x1FFFULL);
}

// ---------- gather + straight-through out + sums + counts ----------
__global__ void k_gather(const float* __restrict__ z, const float* __restrict__ emb,
                         float* __restrict__ out) {
    __shared__ float red[8];
    int e4 = blockIdx.x * blockDim.x + threadIdx.x;
    int row = e4 >> 5;
    int d4  = e4 & 31;
    int k = d_idx[row];
    float4 q  = ((const float4*)(emb + (size_t)k * EDIM))[d4];
    float4 zz = ((const float4*)z)[e4];
    float4 o;
    float s = 0.f, df;
    df = q.x - zz.x; o.x = zz.x + df; s += df * df;
    df = q.y - zz.y; o.y = zz.y + df; s += df * df;
    df = q.z - zz.z; o.z = zz.z + df; s += df * df;
    df = q.w - zz.w; o.w = zz.w + df; s += df * df;
    ((float4*)out)[e4] = o;
    if (d4 == 0) atomicAdd(&d_counts[k], 1);
#pragma unroll
    for (int off = 16; off; off >>= 1) s += __shfl_xor_sync(0xffffffffu, s, off);
    int lane = threadIdx.x & 31, w = threadIdx.x >> 5;
    if (lane == 0) red[w] = s;
    __syncthreads();
    if (threadIdx.x == 0) {
        float bs = 0.f;
#pragma unroll
        for (int i = 0; i < 8; i++) bs += red[i];
        atomicAdd(&d_sumsq, (double)bs);
    }
}

// ---------- perplexity + commit loss ----------
__global__ void k_final(float* __restrict__ out, int n_rows) {
    __shared__ float red[256];
    float acc = 0.f;
    float invN = 1.f / (float)n_rows;
    for (int k = threadIdx.x; k < K_CODES; k += 256) {
        float e = (float)d_counts[k] * invN;
        acc += e * logf(e + 1e-8f);
    }
    red[threadIdx.x] = acc;
    __syncthreads();
    for (int s = 128; s; s >>= 1) {
        if (threadIdx.x < s) red[threadIdx.x] += red[threadIdx.x + s];
        __syncthreads();
    }
    if (threadIdx.x == 0) {
        float m = (float)(d_sumsq / (double)((size_t)n_rows * EDIM));
        out[(size_t)n_rows * EDIM]     = 0.25f * m + m;
        out[(size_t)n_rows * EDIM + 1] = expf(-red[0]);
    }
}

extern "C" void kernel_launch(void* const* d_in, const int* in_sizes, int n_in,
                              void* d_out, int out_size) {
    const float* z   = (const float*)d_in[0];
    const float* emb = (const float*)d_in[1];
    float* out = (float*)d_out;
    int n_rows = in_sizes[0] / EDIM;                  // 32768

    cudaFuncSetAttribute(k_main, cudaFuncAttributeMaxDynamicSharedMemorySize, SMEM_TOTAL);

    k_init<<<K_CODES / 256, 256>>>(emb);
    k_main<<<n_rows / TM, 256, SMEM_TOTAL>>>(z, emb);
    k_gather<<<(n_rows * (EDIM / 4)) / 256, 256>>>(z, emb, out);
    k_final<<<1, 256>>>(out, n_rows);
}

// round 5
// speedup vs baseline: 2.2198x; 1.7905x over previous
#include <cuda_runtime.h>

typedef unsigned long long u64;
typedef unsigned int u32;

#define K_CODES 8192
#define EDIM 128
#define TM 128
#define TN 128
#define N_TILES (K_CODES / TN)    // 64
#define SA 132                    // padded row stride (floats)
#define A_FLOATS (128 * SA)
#define STAGE_FLOATS (128 * SA)
#define SMEM_TOTAL ((A_FLOATS + 2 * STAGE_FLOATS + 128) * 4 + 128 * 8)
#define DELTA 6e-4f

__device__ float  d_esq[K_CODES];
__device__ float  d_zsq[32768];
__device__ int    d_counts[K_CODES];
__device__ int    d_idx[32768];
__device__ u64    d_minkey[32768];
__device__ u64    d_cand[32768 * 32];
__device__ double d_sumsq;

// ---------------- helpers ----------------
__device__ __forceinline__ u32 smem_u32(const void* p) {
    u32 a; asm("{ .reg .u64 t; cvta.to.shared.u64 t, %1; cvt.u32.u64 %0, t; }" : "=r"(a) : "l"(p));
    return a;
}
__device__ __forceinline__ u32 tf32b(float x) {
    u32 r; asm("cvt.rna.tf32.f32 %0, %1;" : "=r"(r) : "f"(x)); return r;
}
__device__ __forceinline__ u32 fkey(float s) {
    u32 b = __float_as_uint(s);
    return (b & 0x80000000u) ? ~b : (b | 0x80000000u);
}
__device__ __forceinline__ float unfkey(u32 k) {
    u32 b = (k & 0x80000000u) ? (k & 0x7FFFFFFFu) : ~k;
    return __uint_as_float(b);
}
__device__ __forceinline__ void cp16(u32 dst, const void* src) {
    asm volatile("cp.async.cg.shared.global [%0], [%1], 16;" :: "r"(dst), "l"(src) : "memory");
}
__device__ __forceinline__ void mma8(float* c, const u32* a, const u32* b) {
    asm volatile(
        "mma.sync.aligned.m16n8k8.row.col.f32.tf32.tf32.f32 "
        "{%0,%1,%2,%3}, {%4,%5,%6,%7}, {%8,%9}, {%0,%1,%2,%3};"
        : "+f"(c[0]), "+f"(c[1]), "+f"(c[2]), "+f"(c[3])
        : "r"(a[0]), "r"(a[1]), "r"(a[2]), "r"(a[3]), "r"(b[0]), "r"(b[1]));
}
__device__ __forceinline__ void top2(u64& b1, u64& b2, u64 k) {
    if (k < b1) { b2 = b1; b1 = k; }
    else if (k < b2) { b2 = k; }
}

// ---------- kernel 0: |e_k|^2 + zero counts/sumsq ----------
__global__ void k_init(const float* __restrict__ emb) {
    int k = blockIdx.x * blockDim.x + threadIdx.x;
    if (k < K_CODES) {
        const float4* row = (const float4*)(emb + (size_t)k * EDIM);
        float s = 0.f;
#pragma unroll
        for (int i = 0; i < EDIM / 4; i++) {
            float4 v = row[i];
            s += v.x * v.x + v.y * v.y + v.z * v.z + v.w * v.w;
        }
        d_esq[k] = s;
        d_counts[k] = 0;
    }
    if (blockIdx.x == 0 && threadIdx.x == 0) d_sumsq = 0.0;
}

// ---------- main: 1-term tf32 screening GEMM + top-2 candidates ----------
extern "C" __global__ void __launch_bounds__(256, 1)
k_main(const float* __restrict__ z, const float* __restrict__ emb) {
    extern __shared__ float sm[];
    float* As    = sm;                              // [128][132] tf32-rounded z
    float* Bs    = sm + A_FLOATS;                   // 2 stages [128][132] fp32 emb
    float* zsmem = Bs + 2 * STAGE_FLOATS;           // unused slot keeper
    u64*   sbest = (u64*)(zsmem + 128);             // [128]

    const int tid  = threadIdx.x;
    const int wid  = tid >> 5;
    const int lane = tid & 31;
    const int lr   = lane >> 2;
    const int lc   = lane & 3;
    const int wm   = (wid & 1) * 64;
    const int wn   = (wid >> 1) * 32;
    const int rowBase = blockIdx.x * TM;

    const u32 smb   = smem_u32(sm);
    const u32 bsOff = smb + A_FLOATS * 4;

    // prefetch tile 0
    {
        const float* src = emb;
#pragma unroll
        for (int i = 0; i < 16; i++) {
            int idx = tid + i * 256;
            int r = idx >> 5, seg = idx & 31;
            cp16(bsOff + (u32)(r * (SA * 4) + seg * 16), src + r * EDIM + seg * 4);
        }
        asm volatile("cp.async.commit_group;" ::: "memory");
    }

    // prologue: zsq (full precision, round-2-identical order), As = tf32(z)
    if (tid < 128) {
        const float4* zr = (const float4*)(z + (size_t)(rowBase + tid) * EDIM);
        float s = 0.f;
#pragma unroll
        for (int q = 0; q < 32; q++) {
            float4 v = zr[q];
            s += v.x * v.x + v.y * v.y + v.z * v.z + v.w * v.w;
            float4 h;
            h.x = __uint_as_float(tf32b(v.x));
            h.y = __uint_as_float(tf32b(v.y));
            h.z = __uint_as_float(tf32b(v.z));
            h.w = __uint_as_float(tf32b(v.w));
            *(float4*)(As + tid * SA + q * 4) = h;
        }
        d_zsq[rowBase + tid] = s;
        zsmem[tid] = s;
        sbest[tid] = ~0ULL;
    }
    __syncthreads();

    float zrow[4][2];
#pragma unroll
    for (int i = 0; i < 4; i++) {
        zrow[i][0] = zsmem[wm + i * 16 + lr];
        zrow[i][1] = zsmem[wm + i * 16 + lr + 8];
    }

    u64 best1[4][2], best2[4][2];
#pragma unroll
    for (int i = 0; i < 4; i++)
#pragma unroll
        for (int s = 0; s < 2; s++) { best1[i][s] = ~0ULL; best2[i][s] = ~0ULL; }

#pragma unroll 1
    for (int tile = 0; tile < N_TILES; tile++) {
        const int st = tile & 1;
        const int colBase = tile * TN;

        float eq[4][2];
#pragma unroll
        for (int j = 0; j < 4; j++) {
            int c0 = colBase + wn + j * 8 + 2 * lc;
            eq[j][0] = d_esq[c0];
            eq[j][1] = d_esq[c0 + 1];
        }

        if (tile + 1 < N_TILES) {
            const float* src = emb + (size_t)(colBase + TN) * EDIM;
            u32 dstb = bsOff + (st ^ 1) * (STAGE_FLOATS * 4);
#pragma unroll
            for (int i = 0; i < 16; i++) {
                int idx = tid + i * 256;
                int r = idx >> 5, seg = idx & 31;
                cp16(dstb + (u32)(r * (SA * 4) + seg * 16), src + r * EDIM + seg * 4);
            }
            asm volatile("cp.async.commit_group;" ::: "memory");
            asm volatile("cp.async.wait_group 1;" ::: "memory");
        } else {
            asm volatile("cp.async.wait_group 0;" ::: "memory");
        }
        __syncthreads();

        const float* Bt = Bs + st * STAGE_FLOATS;

        float acc[4][4][4];
#pragma unroll
        for (int i = 0; i < 4; i++)
#pragma unroll
            for (int j = 0; j < 4; j++)
#pragma unroll
                for (int c = 0; c < 4; c++) acc[i][j][c] = 0.f;

#pragma unroll 1
        for (int kb = 0; kb < 16; kb++) {
            const int k0 = kb * 8;
            u32 ahi[4][4];
#pragma unroll
            for (int i = 0; i < 4; i++) {
                const u32* a0 = (const u32*)(As + (wm + i * 16 + lr) * SA + k0);
                const u32* a1 = a0 + 8 * SA;
                ahi[i][0] = a0[lc];
                ahi[i][1] = a1[lc];
                ahi[i][2] = a0[4 + lc];
                ahi[i][3] = a1[4 + lc];
            }
            u32 bhi[4][2];
#pragma unroll
            for (int j = 0; j < 4; j++) {
                const float* bp = Bt + (wn + j * 8 + lr) * SA + k0;
                bhi[j][0] = tf32b(bp[lc]);
                bhi[j][1] = tf32b(bp[4 + lc]);
            }
#pragma unroll
            for (int i = 0; i < 4; i++)
#pragma unroll
                for (int j = 0; j < 4; j++) mma8(acc[i][j], ahi[i], bhi[j]);
        }

        // approx epilogue: same grid formula, track top-2 per (row-pair)
#pragma unroll
        for (int i = 0; i < 4; i++) {
#pragma unroll
            for (int j = 0; j < 4; j++) {
                int cg0 = colBase + wn + j * 8 + 2 * lc;
#pragma unroll
                for (int s = 0; s < 2; s++) {
                    float t0 = zrow[i][s] + eq[j][0];
                    float t1 = zrow[i][s] + eq[j][1];
                    float d0 = t0 - 2.f * acc[i][j][2 * s + 0];
                    float d1 = t1 - 2.f * acc[i][j][2 * s + 1];
                    u64 k0 = ((u64)fkey(d0) << 13) | (u32)cg0;
                    u64 k1 = ((u64)fkey(d1) << 13) | (u32)(cg0 + 1);
                    top2(best1[i][s], best2[i][s], k0);
                    top2(best1[i][s], best2[i][s], k1);
                }
            }
        }
        __syncthreads();
    }

    const int slot = (wid >> 1) * 4 + lc;            // 0..15 per row
#pragma unroll
    for (int i = 0; i < 4; i++)
#pragma unroll
        for (int s = 0; s < 2; s++) {
            int rl = wm + i * 16 + lr + s * 8;
            atomicMin(&sbest[rl], best1[i][s]);
            u64* c = &d_cand[(size_t)(rowBase + rl) * 32 + slot * 2];
            c[0] = best1[i][s];
            c[1] = best2[i][s];
        }
    __syncthreads();
    if (tid < 128) d_minkey[rowBase + tid] = sbest[tid];
}

// ---------- rescore: exact fp32 dot on candidates, grid-exact argmin ----------
__global__ void k_rescore(const float* __restrict__ z, const float* __restrict__ emb) {
    int warp = (blockIdx.x * blockDim.x + threadIdx.x) >> 5;
    int lane = threadIdx.x & 31;
    int r = warp;                                    // one row per warp

    u64 key = d_cand[(size_t)r * 32 + lane];
    u64 mk  = d_minkey[r];
    float dmin = unfkey((u32)(mk >> 13));
    u32 thr = fkey(dmin + DELTA);

    u64 mykey = ~0ULL;
    if ((u32)(key >> 13) <= thr) {
        int idx = (int)(key & 0x1FFFULL);
        const float4* zr = (const float4*)(z + (size_t)r * EDIM);
        const float4* er = (const float4*)(emb + (size_t)idx * EDIM);
        float dot = 0.f;
#pragma unroll
        for (int q = 0; q < 32; q++) {
            float4 a = zr[q], b = er[q];
            dot += a.x * b.x + a.y * b.y + a.z * b.z + a.w * b.w;
        }
        float t = d_zsq[r] + d_esq[idx];             // fl(zsq+esq)
        float d = t - 2.f * dot;                     // fl(t - 2*dot): grid-exact
        mykey = ((u64)fkey(d) << 13) | (u32)idx;
    }
#pragma unroll
    for (int off = 16; off; off >>= 1) {
        u64 o = __shfl_xor_sync(0xffffffffu, mykey, off);
        if (o < mykey) mykey = o;
    }
    if (lane == 0) d_idx[r] = (int)(mykey & 0x1FFFULL);
}

// ---------- gather + straight-through out + sums + counts ----------
__global__ void k_gather(const float* __restrict__ z, const float* __restrict__ emb,
                         float* __restrict__ out) {
    __shared__ float red[8];
    int e4 = blockIdx.x * blockDim.x + threadIdx.x;
    int row = e4 >> 5;
    int d4  = e4 & 31;
    int k = d_idx[row];
    float4 q  = ((const float4*)(emb + (size_t)k * EDIM))[d4];
    float4 zz = ((const float4*)z)[e4];
    float4 o;
    float s = 0.f, df;
    df = q.x - zz.x; o.x = zz.x + df; s += df * df;
    df = q.y - zz.y; o.y = zz.y + df; s += df * df;
    df = q.z - zz.z; o.z = zz.z + df; s += df * df;
    df = q.w - zz.w; o.w = zz.w + df; s += df * df;
    ((float4*)out)[e4] = o;
    if (d4 == 0) atomicAdd(&d_counts[k], 1);
#pragma unroll
    for (int off = 16; off; off >>= 1) s += __shfl_xor_sync(0xffffffffu, s, off);
    int lane = threadIdx.x & 31, w = threadIdx.x >> 5;
    if (lane == 0) red[w] = s;
    __syncthreads();
    if (threadIdx.x == 0) {
        float bs = 0.f;
#pragma unroll
        for (int i = 0; i < 8; i++) bs += red[i];
        atomicAdd(&d_sumsq, (double)bs);
    }
}

// ---------- perplexity + commit loss ----------
__global__ void k_final(float* __restrict__ out, int n_rows) {
    __shared__ float red[256];
    float acc = 0.f;
    float invN = 1.f / (float)n_rows;
    for (int k = threadIdx.x; k < K_CODES; k += 256) {
        float e = (float)d_counts[k] * invN;
        acc += e * logf(e + 1e-8f);
    }
    red[threadIdx.x] = acc;
    __syncthreads();
    for (int s = 128; s; s >>= 1) {
        if (threadIdx.x < s) red[threadIdx.x] += red[threadIdx.x + s];
        __syncthreads();
    }
    if (threadIdx.x == 0) {
        float m = (float)(d_sumsq / (double)((size_t)n_rows * EDIM));
        out[(size_t)n_rows * EDIM]     = 0.25f * m + m;
        out[(size_t)n_rows * EDIM + 1] = expf(-red[0]);
    }
}

extern "C" void kernel_launch(void* const* d_in, const int* in_sizes, int n_in,
                              void* d_out, int out_size) {
    const float* z   = (const float*)d_in[0];
    const float* emb = (const float*)d_in[1];
    float* out = (float*)d_out;
    int n_rows = in_sizes[0] / EDIM;                  // 32768

    cudaFuncSetAttribute(k_main, cudaFuncAttributeMaxDynamicSharedMemorySize, SMEM_TOTAL);

    k_init<<<K_CODES / 256, 256>>>(emb);
    k_main<<<n_rows / TM, 256, SMEM_TOTAL>>>(z, emb);
    k_rescore<<<n_rows / 8, 256>>>(z, emb);
    k_gather<<<(n_rows * (EDIM / 4)) / 256, 256>>>(z, emb, out);
    k_final<<<1, 256>>>(out, n_rows);
}

// round 6
// speedup vs baseline: 3.0675x; 1.3819x over previous
#include <cuda_runtime.h>
#include <cuda_fp16.h>

typedef unsigned long long u64;
typedef unsigned int u32;

#define K_CODES 8192
#define EDIM 128
#define TM 128
#define TN 128
#define N_TILES (K_CODES / TN)    // 64
#define SAH 136                   // padded row stride (halfs) = 68 words
#define SAW 68                    // row stride in 32-bit words
#define A_BYTES (128 * SAH * 2)   // 34816
#define STAGE_BYTES (128 * SAH * 2)
#define ZS_OFF (3 * A_BYTES)                 // float[128]
#define SB_OFF (ZS_OFF + 512)                // u64[128]
#define SMEM_TOTAL (SB_OFF + 1024)
#define DELTA 2e-3f

__device__ float  d_esq[K_CODES];
__device__ float  d_zsq[32768];
__device__ __align__(16) u32 d_emb_h[K_CODES * 64];   // fp16 image of emb
__device__ int    d_counts[K_CODES];
__device__ int    d_idx[32768];
__device__ u64    d_minkey[32768];
__device__ u64    d_cand[32768 * 32];
__device__ double d_sumsq;

// ---------------- helpers ----------------
__device__ __forceinline__ u32 smem_u32(const void* p) {
    u32 a; asm("{ .reg .u64 t; cvta.to.shared.u64 t, %1; cvt.u32.u64 %0, t; }" : "=r"(a) : "l"(p));
    return a;
}
__device__ __forceinline__ u32 fkey(float s) {
    u32 b = __float_as_uint(s);
    return (b & 0x80000000u) ? ~b : (b | 0x80000000u);
}
__device__ __forceinline__ float unfkey(u32 k) {
    u32 b = (k & 0x80000000u) ? (k & 0x7FFFFFFFu) : ~k;
    return __uint_as_float(b);
}
__device__ __forceinline__ void cp16(u32 dst, const void* src) {
    asm volatile("cp.async.cg.shared.global [%0], [%1], 16;" :: "r"(dst), "l"(src) : "memory");
}
__device__ __forceinline__ void mma16(float* c, const u32* a, const u32* b) {
    asm volatile(
        "mma.sync.aligned.m16n8k16.row.col.f32.f16.f16.f32 "
        "{%0,%1,%2,%3}, {%4,%5,%6,%7}, {%8,%9}, {%0,%1,%2,%3};"
        : "+f"(c[0]), "+f"(c[1]), "+f"(c[2]), "+f"(c[3])
        : "r"(a[0]), "r"(a[1]), "r"(a[2]), "r"(a[3]), "r"(b[0]), "r"(b[1]));
}
__device__ __forceinline__ u32 h2u(float x, float y) {
    __half2 h = __floats2half2_rn(x, y);
    return *(u32*)&h;
}
__device__ __forceinline__ void top2(u64& b1, u64& b2, u64 k) {
    if (k < b1) { b2 = b1; b1 = k; }
    else if (k < b2) { b2 = k; }
}

// ---------- kernel 0: |e_k|^2, fp16 emb image, zero counts/sumsq ----------
__global__ void k_init(const float* __restrict__ emb) {
    int k = blockIdx.x * blockDim.x + threadIdx.x;
    if (k < K_CODES) {
        const float4* row = (const float4*)(emb + (size_t)k * EDIM);
        float s = 0.f;
#pragma unroll
        for (int i = 0; i < EDIM / 4; i++) {
            float4 v = row[i];
            s += v.x * v.x + v.y * v.y + v.z * v.z + v.w * v.w;
            d_emb_h[k * 64 + i * 2]     = h2u(v.x, v.y);
            d_emb_h[k * 64 + i * 2 + 1] = h2u(v.z, v.w);
        }
        d_esq[k] = s;
        d_counts[k] = 0;
    }
    if (blockIdx.x == 0 && threadIdx.x == 0) d_sumsq = 0.0;
}

// ---------- main: fp16 screening GEMM + top-2 candidates ----------
extern "C" __global__ void __launch_bounds__(256, 1)
k_main(const float* __restrict__ z, const float* __restrict__ emb) {
    extern __shared__ char smem[];
    u32*   A32   = (u32*)smem;                        // [128][68] half2 words
    u32*   B32   = (u32*)(smem + A_BYTES);            // 2 stages [128][68]
    float* zsmem = (float*)(smem + ZS_OFF);           // [128]
    u64*   sbest = (u64*)(smem + SB_OFF);             // [128]

    const int tid  = threadIdx.x;
    const int wid  = tid >> 5;
    const int lane = tid & 31;
    const int lr   = lane >> 2;
    const int lc   = lane & 3;
    const int wm   = (wid & 1) * 64;
    const int wn   = (wid >> 1) * 32;
    const int rowBase = blockIdx.x * TM;

    const u32 smb   = smem_u32(smem);
    const u32 bsOff = smb + A_BYTES;

    // prefetch tile 0 (fp16 image: 16B = 4 words = 8 halfs)
    {
#pragma unroll
        for (int i = 0; i < 8; i++) {
            int idx = tid + i * 256;                  // 0..2047 chunks
            int r = idx >> 4, seg = idx & 15;
            cp16(bsOff + (u32)(r * (SAH * 2) + seg * 16), d_emb_h + r * 64 + seg * 4);
        }
        asm volatile("cp.async.commit_group;" ::: "memory");
    }

    // prologue: zsq (exact, round-2-identical order), As = fp16(z)
    if (tid < 128) {
        const float4* zr = (const float4*)(z + (size_t)(rowBase + tid) * EDIM);
        float s = 0.f;
#pragma unroll
        for (int q = 0; q < 32; q++) {
            float4 v = zr[q];
            s += v.x * v.x + v.y * v.y + v.z * v.z + v.w * v.w;
            A32[tid * SAW + q * 2]     = h2u(v.x, v.y);
            A32[tid * SAW + q * 2 + 1] = h2u(v.z, v.w);
        }
        d_zsq[rowBase + tid] = s;
        zsmem[tid] = s;
        sbest[tid] = ~0ULL;
    }
    __syncthreads();

    float zrow[4][2];
#pragma unroll
    for (int i = 0; i < 4; i++) {
        zrow[i][0] = zsmem[wm + i * 16 + lr];
        zrow[i][1] = zsmem[wm + i * 16 + lr + 8];
    }

    u64 best1[4][2], best2[4][2];
#pragma unroll
    for (int i = 0; i < 4; i++)
#pragma unroll
        for (int s = 0; s < 2; s++) { best1[i][s] = ~0ULL; best2[i][s] = ~0ULL; }

#pragma unroll 1
    for (int tile = 0; tile < N_TILES; tile++) {
        const int st = tile & 1;
        const int colBase = tile * TN;

        float eq[4][2];
#pragma unroll
        for (int j = 0; j < 4; j++) {
            int c0 = colBase + wn + j * 8 + 2 * lc;
            eq[j][0] = d_esq[c0];
            eq[j][1] = d_esq[c0 + 1];
        }

        if (tile + 1 < N_TILES) {
            const u32* src = d_emb_h + (size_t)(colBase + TN) * 64;
            u32 dstb = bsOff + (st ^ 1) * STAGE_BYTES;
#pragma unroll
            for (int i = 0; i < 8; i++) {
                int idx = tid + i * 256;
                int r = idx >> 4, seg = idx & 15;
                cp16(dstb + (u32)(r * (SAH * 2) + seg * 16), src + r * 64 + seg * 4);
            }
            asm volatile("cp.async.commit_group;" ::: "memory");
            asm volatile("cp.async.wait_group 1;" ::: "memory");
        } else {
            asm volatile("cp.async.wait_group 0;" ::: "memory");
        }
        __syncthreads();

        const u32* Bt = B32 + st * (STAGE_BYTES / 4);

        float acc[4][4][4];
#pragma unroll
        for (int i = 0; i < 4; i++)
#pragma unroll
            for (int j = 0; j < 4; j++)
#pragma unroll
                for (int c = 0; c < 4; c++) acc[i][j][c] = 0.f;

#pragma unroll 1
        for (int kb = 0; kb < 8; kb++) {
            const int kw = kb * 8;                    // word offset (16 halfs / 8 words)
            u32 af[4][4];
#pragma unroll
            for (int i = 0; i < 4; i++) {
                const u32* a0 = A32 + (wm + i * 16 + lr) * SAW + kw;
                af[i][0] = a0[lc];
                af[i][1] = a0[8 * SAW + lc];
                af[i][2] = a0[4 + lc];
                af[i][3] = a0[8 * SAW + 4 + lc];
            }
            u32 bf[4][2];
#pragma unroll
            for (int j = 0; j < 4; j++) {
                const u32* bp = Bt + (wn + j * 8 + lr) * SAW + kw;
                bf[j][0] = bp[lc];
                bf[j][1] = bp[4 + lc];
            }
#pragma unroll
            for (int i = 0; i < 4; i++)
#pragma unroll
                for (int j = 0; j < 4; j++) mma16(acc[i][j], af[i], bf[j]);
        }

        // approx epilogue: grid formula, top-2 per (row, thread)
#pragma unroll
        for (int i = 0; i < 4; i++) {
#pragma unroll
            for (int j = 0; j < 4; j++) {
                int cg0 = colBase + wn + j * 8 + 2 * lc;
#pragma unroll
                for (int s = 0; s < 2; s++) {
                    float t0 = zrow[i][s] + eq[j][0];
                    float t1 = zrow[i][s] + eq[j][1];
                    float d0 = t0 - 2.f * acc[i][j][2 * s + 0];
                    float d1 = t1 - 2.f * acc[i][j][2 * s + 1];
                    u64 k0 = ((u64)fkey(d0) << 13) | (u32)cg0;
                    u64 k1 = ((u64)fkey(d1) << 13) | (u32)(cg0 + 1);
                    top2(best1[i][s], best2[i][s], k0);
                    top2(best1[i][s], best2[i][s], k1);
                }
            }
        }
        __syncthreads();
    }

    const int slot = (wid >> 1) * 4 + lc;             // 0..15 per row
#pragma unroll
    for (int i = 0; i < 4; i++)
#pragma unroll
        for (int s = 0; s < 2; s++) {
            int rl = wm + i * 16 + lr + s * 8;
            atomicMin(&sbest[rl], best1[i][s]);
            u64* c = &d_cand[(size_t)(rowBase + rl) * 32 + slot * 2];
            c[0] = best1[i][s];
            c[1] = best2[i][s];
        }
    __syncthreads();
    if (tid < 128) d_minkey[rowBase + tid] = sbest[tid];
}

// ---------- rescore: exact fp32 dot on candidates, grid-exact argmin ----------
__global__ void k_rescore(const float* __restrict__ z, const float* __restrict__ emb) {
    int warp = (blockIdx.x * blockDim.x + threadIdx.x) >> 5;
    int lane = threadIdx.x & 31;
    int r = warp;

    u64 key = d_cand[(size_t)r * 32 + lane];
    u64 mk  = d_minkey[r];
    float dmin = unfkey((u32)(mk >> 13));
    u32 thr = fkey(dmin + DELTA);

    u64 mykey = ~0ULL;
    if ((u32)(key >> 13) <= thr) {
        int idx = (int)(key & 0x1FFFULL);
        const float4* zr = (const float4*)(z + (size_t)r * EDIM);
        const float4* er = (const float4*)(emb + (size_t)idx * EDIM);
        float dot = 0.f;
#pragma unroll
        for (int q = 0; q < 32; q++) {
            float4 a = zr[q], b = er[q];
            dot += a.x * b.x + a.y * b.y + a.z * b.z + a.w * b.w;
        }
        float t = d_zsq[r] + d_esq[idx];              // fl(zsq+esq)
        float d = t - 2.f * dot;                      // fl(t - 2*dot): grid-exact
        mykey = ((u64)fkey(d) << 13) | (u32)idx;
    }
#pragma unroll
    for (int off = 16; off; off >>= 1) {
        u64 o = __shfl_xor_sync(0xffffffffu, mykey, off);
        if (o < mykey) mykey = o;
    }
    if (lane == 0) d_idx[r] = (int)(mykey & 0x1FFFULL);
}

// ---------- gather + straight-through out + sums + counts ----------
__global__ void k_gather(const float* __restrict__ z, const float* __restrict__ emb,
                         float* __restrict__ out) {
    __shared__ float red[8];
    int e4 = blockIdx.x * blockDim.x + threadIdx.x;
    int row = e4 >> 5;
    int d4  = e4 & 31;
    int k = d_idx[row];
    float4 q  = ((const float4*)(emb + (size_t)k * EDIM))[d4];
    float4 zz = ((const float4*)z)[e4];
    float4 o;
    float s = 0.f, df;
    df = q.x - zz.x; o.x = zz.x + df; s += df * df;
    df = q.y - zz.y; o.y = zz.y + df; s += df * df;
    df = q.z - zz.z; o.z = zz.z + df; s += df * df;
    df = q.w - zz.w; o.w = zz.w + df; s += df * df;
    ((float4*)out)[e4] = o;
    if (d4 == 0) atomicAdd(&d_counts[k], 1);
#pragma unroll
    for (int off = 16; off; off >>= 1) s += __shfl_xor_sync(0xffffffffu, s, off);
    int lane = threadIdx.x & 31, w = threadIdx.x >> 5;
    if (lane == 0) red[w] = s;
    __syncthreads();
    if (threadIdx.x == 0) {
        float bs = 0.f;
#pragma unroll
        for (int i = 0; i < 8; i++) bs += red[i];
        atomicAdd(&d_sumsq, (double)bs);
    }
}

// ---------- perplexity + commit loss ----------
__global__ void k_final(float* __restrict__ out, int n_rows) {
    __shared__ float red[256];
    float acc = 0.f;
    float invN = 1.f / (float)n_rows;
    for (int k = threadIdx.x; k < K_CODES; k += 256) {
        float e = (float)d_counts[k] * invN;
        acc += e * logf(e + 1e-8f);
    }
    red[threadIdx.x] = acc;
    __syncthreads();
    for (int s = 128; s; s >>= 1) {
        if (threadIdx.x < s) red[threadIdx.x] += red[threadIdx.x + s];
        __syncthreads();
    }
    if (threadIdx.x == 0) {
        float m = (float)(d_sumsq / (double)((size_t)n_rows * EDIM));
        out[(size_t)n_rows * EDIM]     = 0.25f * m + m;
        out[(size_t)n_rows * EDIM + 1] = expf(-red[0]);
    }
}

extern "C" void kernel_launch(void* const* d_in, const int* in_sizes, int n_in,
                              void* d_out, int out_size) {
    const float* z   = (const float*)d_in[0];
    const float* emb = (const float*)d_in[1];
    float* out = (float*)d_out;
    int n_rows = in_sizes[0] / EDIM;                  // 32768

    cudaFuncSetAttribute(k_main, cudaFuncAttributeMaxDynamicSharedMemorySize, SMEM_TOTAL);

    k_init<<<K_CODES / 256, 256>>>(emb);
    k_main<<<n_rows / TM, 256, SMEM_TOTAL>>>(z, emb);
    k_rescore<<<n_rows / 8, 256>>>(z, emb);
    k_gather<<<(n_rows * (EDIM / 4)) / 256, 256>>>(z, emb, out);
    k_final<<<1, 256>>>(out, n_rows);
}